// round 2
// baseline (speedup 1.0000x reference)
#include <cuda_runtime.h>
#include <cuda_bf16.h>
#include <cstdint>

// Problem constants (fixed shapes from reference)
#define B_     4
#define NX_    400
#define NY_    200
#define NZ_    1
#define C_     256
#define NCAMS_ 6
#define D_     41
#define FH_    8
#define FW_    22
#define NPRIME_ (B_ * NCAMS_ * D_ * FH_ * FW_)   // 173184
#define S_      (NX_ * NY_)                       // 80000 spatial positions per batch
#define OUTELEMS ((size_t)B_ * C_ * S_)           // 81,920,000

// Channel-last accumulator scratch: [B, NX, NY, C]. Zero-initialized at module
// load; every kernel_launch leaves it zeroed again (transpose pass re-zeroes),
// so each graph replay sees a clean accumulator. 328 MB.
__device__ float g_scratch[OUTELEMS];

// ---------------------------------------------------------------------------
// Pass 1: scatter-add points into channel-last scratch.
// One 256-thread block handles 4 points; 64 threads per point, each thread
// owns one float4 (4 channels). x-read fully coalesced (1 KB/point), atomic
// destination contiguous (1 KB/point).
// ---------------------------------------------------------------------------
__global__ __launch_bounds__(256) void scatter_kernel(
    const float* __restrict__ x,
    const int*   __restrict__ geom)
{
    const int p = blockIdx.x * 4 + (threadIdx.x >> 6);   // point index
    const int t = threadIdx.x & 63;                      // float4 slot in C

    // geom row: [gx, gy, gz, gb] as int4
    const int4 g = __ldg(reinterpret_cast<const int4*>(geom) + p);
    // gz is always 0 (NZ=1); voxel base in channel-last scratch
    const size_t base = ((size_t)((g.w * NX_ + g.x) * NY_ + g.y)) * C_;

    const float4 v = __ldg(reinterpret_cast<const float4*>(x + (size_t)p * C_) + t);

    float* dst = g_scratch + base + 4 * t;
    atomicAdd(dst + 0, v.x);
    atomicAdd(dst + 1, v.y);
    atomicAdd(dst + 2, v.z);
    atomicAdd(dst + 3, v.w);
}

// ---------------------------------------------------------------------------
// Pass 2: transpose [b, s, c] -> [b, c, s]  (s = x*NY + y, contiguous in out)
// 32x32 tiles via shared memory, coalesced loads (over c) and stores (over s).
// Writes zero back to scratch after reading, re-arming it for the next replay.
// ---------------------------------------------------------------------------
__global__ __launch_bounds__(256) void transpose_zero_kernel(float* __restrict__ out)
{
    __shared__ float tile[32][33];

    const int b  = blockIdx.z;
    const int c0 = blockIdx.x * 32;   // 256/32 = 8 tiles
    const int s0 = blockIdx.y * 32;   // 80000/32 = 2500 tiles
    const int tx = threadIdx.x;       // 0..31
    const int ty = threadIdx.y;       // 0..7

    float* scr = g_scratch + (size_t)b * S_ * C_;
    float* dst = out       + (size_t)b * C_ * S_;

    #pragma unroll
    for (int j = 0; j < 32; j += 8) {
        const int sr = ty + j;
        const size_t idx = (size_t)(s0 + sr) * C_ + (c0 + tx);
        tile[sr][tx] = scr[idx];
        scr[idx] = 0.0f;              // re-zero scratch for next launch
    }
    __syncthreads();

    #pragma unroll
    for (int j = 0; j < 32; j += 8) {
        const int cr = ty + j;
        dst[(size_t)(c0 + cr) * S_ + (s0 + tx)] = tile[tx][cr];
    }
}

extern "C" void kernel_launch(void* const* d_in, const int* in_sizes, int n_in,
                              void* d_out, int out_size)
{
    const float* x    = (const float*)d_in[0];   // [NPRIME, C] float32
    const int*   geom = (const int*)  d_in[1];   // [NPRIME, 4] int32
    float*       out  = (float*)d_out;           // [B, C*NZ, NX, NY] float32

    // Pass 1: scatter into channel-last scratch (scratch is zero on entry)
    scatter_kernel<<<NPRIME_ / 4, 256>>>(x, geom);

    // Pass 2: transpose to output layout + re-zero scratch
    dim3 grid(C_ / 32, S_ / 32, B_);
    dim3 block(32, 8);
    transpose_zero_kernel<<<grid, block>>>(out);
}

// round 3
// speedup vs baseline: 1.5865x; 1.5865x over previous
#include <cuda_runtime.h>
#include <cuda_bf16.h>
#include <cstdint>

// Problem constants (fixed shapes from reference)
#define B_     4
#define NX_    400
#define NY_    200
#define NZ_    1
#define C_     256
#define NCAMS_ 6
#define D_     41
#define FH_    8
#define FW_    22
#define NPRIME_ (B_ * NCAMS_ * D_ * FH_ * FW_)   // 173184
#define S_      (NX_ * NY_)                       // 80000 spatial positions per batch
#define NVOX    (B_ * S_)                         // 320000 voxels
#define OUTELEMS ((size_t)B_ * C_ * S_)           // 81,920,000

// Channel-last accumulator scratch: [B, NX, NY, C]. Zero at module load;
// pass 2 re-zeroes every touched row, so each graph replay sees zeros. 328 MB.
__device__ float g_scratch[OUTELEMS];
// Touched-voxel flags [B*S]. Set (plain store) in pass 1, cleared in pass 2.
__device__ unsigned char g_flag[NVOX];

// ---------------------------------------------------------------------------
// Pass 1: scatter-add points into channel-last scratch with vectorized
// red.global.add.v4.f32 (one 16B reduction per thread; 64 threads per point).
// ---------------------------------------------------------------------------
__global__ __launch_bounds__(256) void scatter_kernel(
    const float* __restrict__ x,
    const int*   __restrict__ geom)
{
    const int p = blockIdx.x * 4 + (threadIdx.x >> 6);   // point index
    const int t = threadIdx.x & 63;                      // float4 slot in C

    const int4 g = __ldg(reinterpret_cast<const int4*>(geom) + p);
    // gz always 0 (NZ=1). voxel = b*S + x*NY + y
    const int vox = (g.w * NX_ + g.x) * NY_ + g.y;
    const size_t base = (size_t)vox * C_;

    const float4 v = __ldg(reinterpret_cast<const float4*>(x + (size_t)p * C_) + t);

    float* dst = g_scratch + base + 4 * t;
    asm volatile("red.global.add.v4.f32 [%0], {%1, %2, %3, %4};"
                 :: "l"(dst), "f"(v.x), "f"(v.y), "f"(v.z), "f"(v.w)
                 : "memory");

    if (t == 0) g_flag[vox] = 1;   // benign race: all writers store 1
}

// ---------------------------------------------------------------------------
// Pass 2: transpose [b, s, c] -> [b, c, s] and re-zero touched scratch rows.
// One 256-thread block handles 8 s-rows x 256 channels (8 KB tile).
//   Load:  512 float4 slots (2 per thread), fully coalesced LDG.128;
//          untouched rows (flag==0) skip the load and the re-zero store.
//   Store: thread t owns channel c=t; writes 8 contiguous s floats
//          (two STG.128 into one fully-written 32B sector).
// ---------------------------------------------------------------------------
__global__ __launch_bounds__(256) void transpose_zero_kernel(float* __restrict__ out)
{
    __shared__ float tile[8][256];
    __shared__ unsigned char fl[8];

    const int blk   = blockIdx.x;            // 0 .. B*S/8-1
    const int b     = blk / (S_ / 8);
    const int srow0 = (blk % (S_ / 8)) * 8;
    const int tid   = threadIdx.x;

    if (tid < 8) fl[tid] = g_flag[b * S_ + srow0 + tid];
    __syncthreads();

    float* scr = g_scratch + ((size_t)b * S_ + srow0) * C_;

    // Load phase: slot = row*64 + cq  (row 0..7, cq 0..63)
    #pragma unroll
    for (int k = 0; k < 2; k++) {
        const int slot = tid + k * 256;
        const int row  = slot >> 6;
        const int cq   = slot & 63;
        float4 v;
        if (fl[row]) {
            float4* p = reinterpret_cast<float4*>(scr + row * C_) + cq;
            v = *p;
            *p = make_float4(0.f, 0.f, 0.f, 0.f);   // re-zero for next replay
        } else {
            v = make_float4(0.f, 0.f, 0.f, 0.f);
        }
        tile[row][cq * 4 + 0] = v.x;
        tile[row][cq * 4 + 1] = v.y;
        tile[row][cq * 4 + 2] = v.z;
        tile[row][cq * 4 + 3] = v.w;
    }
    __syncthreads();

    // Reset flags (this block exclusively owns these 8 voxels)
    if (tid < 8 && fl[tid]) g_flag[b * S_ + srow0 + tid] = 0;

    // Store phase: thread t = channel c; 8 contiguous s floats = 2x float4
    const int c = tid;
    float* dst = out + (size_t)b * C_ * S_ + (size_t)c * S_ + srow0;
    float4 o0 = make_float4(tile[0][c], tile[1][c], tile[2][c], tile[3][c]);
    float4 o1 = make_float4(tile[4][c], tile[5][c], tile[6][c], tile[7][c]);
    reinterpret_cast<float4*>(dst)[0] = o0;
    reinterpret_cast<float4*>(dst)[1] = o1;
}

extern "C" void kernel_launch(void* const* d_in, const int* in_sizes, int n_in,
                              void* d_out, int out_size)
{
    const float* x    = (const float*)d_in[0];   // [NPRIME, C] float32
    const int*   geom = (const int*)  d_in[1];   // [NPRIME, 4] int32
    float*       out  = (float*)d_out;           // [B, C*NZ, NX, NY] float32

    // Pass 1: scatter into channel-last scratch (scratch is zero on entry)
    scatter_kernel<<<NPRIME_ / 4, 256>>>(x, geom);

    // Pass 2: transpose to output layout + re-zero touched scratch rows
    transpose_zero_kernel<<<NVOX / 8, 256>>>(out);
}

// round 4
// speedup vs baseline: 5.1282x; 3.2324x over previous
#include <cuda_runtime.h>
#include <cuda_bf16.h>
#include <cstdint>

// Problem constants (fixed shapes from reference)
#define B_     4
#define NX_    400
#define NY_    200
#define NZ_    1
#define C_     256
#define NPRIME_ 173184                            // B*6*41*8*22
#define S_      (NX_ * NY_)                       // 80000
#define NVOX    (B_ * S_)                         // 320000
#define OUTELEMS ((size_t)B_ * C_ * S_)           // 81,920,000

// Channel-last accumulator scratch [B, S, C]. Zero at module load; pass 2
// re-zeroes touched rows so every graph replay sees zeros. 328 MB.
__device__ float g_scratch[OUTELEMS];
// Touched-voxel flags [B*S]. Set in pass 1 (plain store), cleared in pass 2.
__device__ unsigned char g_flag[NVOX];

// ---------------------------------------------------------------------------
// Pass 1: scatter-add with vectorized red.global.add.v4.f32.
// 64 threads per point, each owns one float4 of C.
// ---------------------------------------------------------------------------
__global__ __launch_bounds__(256) void scatter_kernel(
    const float* __restrict__ x,
    const int*   __restrict__ geom)
{
    const int p = blockIdx.x * 4 + (threadIdx.x >> 6);
    const int t = threadIdx.x & 63;

    const int4 g = __ldg(reinterpret_cast<const int4*>(geom) + p);
    const int vox = (g.w * NX_ + g.x) * NY_ + g.y;        // gz==0 (NZ=1)
    const size_t base = (size_t)vox * C_;

    const float4 v = __ldg(reinterpret_cast<const float4*>(x + (size_t)p * C_) + t);

    float* dst = g_scratch + base + 4 * t;
    asm volatile("red.global.add.v4.f32 [%0], {%1, %2, %3, %4};"
                 :: "l"(dst), "f"(v.x), "f"(v.y), "f"(v.z), "f"(v.w)
                 : "memory");

    if (t == 0) g_flag[vox] = 1;
}

// ---------------------------------------------------------------------------
// Pass 2: transpose [b, s, c] -> [b, c, s], tile = 32 s-rows x 256 channels.
// Every channel's 32 s-values form one complete 128B output line, written by
// a single STG.128 warp-phase -> no partial-line writes, full DRAM efficiency.
// Touched scratch rows are re-zeroed; untouched rows skip global traffic.
// ---------------------------------------------------------------------------
__global__ __launch_bounds__(256) void transpose_zero_kernel(float* __restrict__ out)
{
    // tile4[s][cq]: s-row s, channel-quad cq (c = 4*cq+d). Pitch 65 quads:
    // STS.128 writes conflict-free; scalar column reads are 4-way (OK).
    __shared__ float4 tile4[32][65];
    __shared__ unsigned char fl[32];

    const int blk = blockIdx.x;              // 0 .. B*S/32-1
    const int b   = blk / (S_ / 32);
    const int s0  = (blk % (S_ / 32)) * 32;
    const int tid = threadIdx.x;

    if (tid < 32) fl[tid] = g_flag[b * S_ + s0 + tid];
    __syncthreads();

    float* scr = g_scratch + ((size_t)b * S_ + s0) * C_;

    // ---- Load phase: 2048 float4, 8 per thread. slot = k*256+tid;
    // row = slot>>6 (s within tile), cq = slot&63. Coalesced LDG.128.
    const int trow0 = tid >> 6;             // 0..3
    const int tcq   = tid & 63;
    float4 v[8];
    const float4 zero4 = make_float4(0.f, 0.f, 0.f, 0.f);

    #pragma unroll
    for (int k = 0; k < 8; k++) {
        const int row = 4 * k + trow0;
        if (fl[row]) {
            v[k] = *(reinterpret_cast<const float4*>(scr + row * C_) + tcq);
        } else {
            v[k] = zero4;
        }
    }
    // Re-zero touched rows (per-thread same-address ordering after the load).
    #pragma unroll
    for (int k = 0; k < 8; k++) {
        const int row = 4 * k + trow0;
        if (fl[row])
            *(reinterpret_cast<float4*>(scr + row * C_) + tcq) = zero4;
    }
    // Stage to smem (vector STS, conflict-free).
    #pragma unroll
    for (int k = 0; k < 8; k++)
        tile4[4 * k + trow0][tcq] = v[k];

    __syncthreads();

    // Clear flags (this block exclusively owns these 32 voxels).
    if (tid < 32 && fl[tid]) g_flag[b * S_ + s0 + tid] = 0;

    // ---- Store phase: warp w, lane l. Iteration i: channel c = w*32+i*4+(l>>3),
    // s-quad q = l&7. Each STG.128 instruction writes 4 complete 128B lines.
    const int w = tid >> 5;
    const int l = tid & 31;
    const int q = l & 7;
    const int cu = l >> 3;

    float* dstb = out + (size_t)b * C_ * S_ + s0;

    #pragma unroll
    for (int i = 0; i < 8; i++) {
        const int c = w * 32 + i * 4 + cu;
        // gather 4 consecutive s for channel c (scalar LDS, 4-way conflicts)
        float4 o;
        o.x = reinterpret_cast<const float*>(&tile4[4 * q + 0][c >> 2])[c & 3];
        o.y = reinterpret_cast<const float*>(&tile4[4 * q + 1][c >> 2])[c & 3];
        o.z = reinterpret_cast<const float*>(&tile4[4 * q + 2][c >> 2])[c & 3];
        o.w = reinterpret_cast<const float*>(&tile4[4 * q + 3][c >> 2])[c & 3];
        *reinterpret_cast<float4*>(dstb + (size_t)c * S_ + 4 * q) = o;
    }
}

extern "C" void kernel_launch(void* const* d_in, const int* in_sizes, int n_in,
                              void* d_out, int out_size)
{
    const float* x    = (const float*)d_in[0];   // [NPRIME, C] float32
    const int*   geom = (const int*)  d_in[1];   // [NPRIME, 4] int32
    float*       out  = (float*)d_out;           // [B, C, NX, NY] float32

    scatter_kernel<<<NPRIME_ / 4, 256>>>(x, geom);
    transpose_zero_kernel<<<NVOX / 32, 256>>>(out);
}

// round 5
// speedup vs baseline: 5.9033x; 1.1512x over previous
#include <cuda_runtime.h>
#include <cuda_bf16.h>
#include <cstdint>

// Problem constants (fixed shapes from reference)
#define B_     4
#define NX_    400
#define NY_    200
#define NZ_    1
#define C_     256
#define NPRIME_ 173184                            // B*6*41*8*22
#define S_      (NX_ * NY_)                       // 80000
#define NVOX    (B_ * S_)                         // 320000
#define OUTELEMS ((size_t)B_ * C_ * S_)           // 81,920,000

// Channel-last accumulator scratch [B, S, C]. Zero at module load; pass 2
// re-zeroes touched rows so every graph replay sees zeros. 328 MB.
__device__ float g_scratch[OUTELEMS];
// Touched-voxel flags [B*S]. Set in pass 1 (plain store), cleared in pass 2.
__device__ unsigned char g_flag[NVOX];

// ---------------------------------------------------------------------------
// Pass 1: scatter-add with vectorized red.global.add.v4.f32.
// 64 threads per point, each owns one float4 of C.
// ---------------------------------------------------------------------------
__global__ __launch_bounds__(256) void scatter_kernel(
    const float* __restrict__ x,
    const int*   __restrict__ geom)
{
    const int p = blockIdx.x * 4 + (threadIdx.x >> 6);
    const int t = threadIdx.x & 63;

    const int4 g = __ldg(reinterpret_cast<const int4*>(geom) + p);
    const int vox = (g.w * NX_ + g.x) * NY_ + g.y;        // gz==0 (NZ=1)
    const size_t base = (size_t)vox * C_;

    const float4 v = __ldg(reinterpret_cast<const float4*>(x + (size_t)p * C_) + t);

    float* dst = g_scratch + base + 4 * t;
    asm volatile("red.global.add.v4.f32 [%0], {%1, %2, %3, %4};"
                 :: "l"(dst), "f"(v.x), "f"(v.y), "f"(v.z), "f"(v.w)
                 : "memory");

    if (t == 0) g_flag[vox] = 1;
}

// ---------------------------------------------------------------------------
// Pass 2: transpose [b, s, c] -> [b, c, s], tile = 32 s-rows x 256 channels.
// smem layout XOR-swizzled: tile4[row][cq ^ (row>>2)], no padding (32 KB).
//   - load-phase STS.128: conflict-free
//   - store-phase scalar LDS: bank = (4*((cq^q)&7) + cu) mod 32, bijective
//     over the 32 lanes -> conflict-free (was 4-way with padded layout)
// Each channel's 32 s-values form one complete 128B output line.
// Touched scratch rows are re-zeroed; untouched rows skip global traffic.
// ---------------------------------------------------------------------------
__global__ __launch_bounds__(256) void transpose_zero_kernel(float* __restrict__ out)
{
    __shared__ float4 tile4[32][64];          // [s-row][swizzled channel-quad]
    __shared__ unsigned char fl[32];

    const int blk = blockIdx.x;               // 0 .. B*S/32-1
    const int b   = blk / (S_ / 32);
    const int s0  = (blk % (S_ / 32)) * 32;
    const int tid = threadIdx.x;

    if (tid < 32) fl[tid] = g_flag[b * S_ + s0 + tid];
    __syncthreads();

    float* scr = g_scratch + ((size_t)b * S_ + s0) * C_;

    // ---- Load phase: 2048 float4, 8 per thread.
    // row = 4k + (tid>>6), cq = tid&63. Coalesced LDG.128, batched for MLP.
    const int trow0 = tid >> 6;               // 0..3
    const int tcq   = tid & 63;
    float4 v[8];
    const float4 zero4 = make_float4(0.f, 0.f, 0.f, 0.f);

    #pragma unroll
    for (int k = 0; k < 8; k++) {
        const int row = 4 * k + trow0;
        v[k] = fl[row] ? *(reinterpret_cast<const float4*>(scr + row * C_) + tcq)
                       : zero4;
    }
    // Re-zero touched rows (same-thread same-address ordering after the load).
    #pragma unroll
    for (int k = 0; k < 8; k++) {
        const int row = 4 * k + trow0;
        if (fl[row])
            *(reinterpret_cast<float4*>(scr + row * C_) + tcq) = zero4;
    }
    // Stage to smem, XOR-swizzled: f(row) = row>>2 = k.
    #pragma unroll
    for (int k = 0; k < 8; k++)
        tile4[4 * k + trow0][tcq ^ k] = v[k];

    __syncthreads();

    // Clear flags (this block exclusively owns these 32 voxels).
    if (tid < 32 && fl[tid]) g_flag[b * S_ + s0 + tid] = 0;

    // ---- Store phase: warp w, lane l; q = l&7 (s-quad), cu = l>>3.
    // Iteration i: channel c = w*32 + 4i + cu  ->  cq = w*8 + i, c&3 = cu.
    // Reads tile4[4q+r][cq ^ q] component cu; conflict-free by swizzle.
    const int w  = tid >> 5;
    const int l  = tid & 31;
    const int q  = l & 7;
    const int cu = l >> 3;

    float* dstb = out + (size_t)b * C_ * S_ + s0;

    #pragma unroll
    for (int i = 0; i < 8; i++) {
        const int cq = w * 8 + i;
        const int c  = 4 * cq + cu;
        float4 o;
        o.x = reinterpret_cast<const float*>(&tile4[4 * q + 0][cq ^ q])[cu];
        o.y = reinterpret_cast<const float*>(&tile4[4 * q + 1][cq ^ q])[cu];
        o.z = reinterpret_cast<const float*>(&tile4[4 * q + 2][cq ^ q])[cu];
        o.w = reinterpret_cast<const float*>(&tile4[4 * q + 3][cq ^ q])[cu];
        *reinterpret_cast<float4*>(dstb + (size_t)c * S_ + 4 * q) = o;
    }
}

extern "C" void kernel_launch(void* const* d_in, const int* in_sizes, int n_in,
                              void* d_out, int out_size)
{
    const float* x    = (const float*)d_in[0];   // [NPRIME, C] float32
    const int*   geom = (const int*)  d_in[1];   // [NPRIME, 4] int32
    float*       out  = (float*)d_out;           // [B, C, NX, NY] float32

    scatter_kernel<<<NPRIME_ / 4, 256>>>(x, geom);
    transpose_zero_kernel<<<NVOX / 32, 256>>>(out);
}

// round 6
// speedup vs baseline: 8.7119x; 1.4758x over previous
#include <cuda_runtime.h>
#include <cuda_bf16.h>
#include <cstdint>

// Problem constants (fixed shapes from reference)
#define B_     4
#define NX_    400
#define NY_    200
#define NZ_    1
#define C_     256
#define NPRIME_ 173184                            // B*6*41*8*22
#define S_      (NX_ * NY_)                       // 80000
#define NVOX    (B_ * S_)                         // 320000

// Per-voxel point chains. g_head: 0 = empty, else point_index+1.
// Zero at module load; the gather pass re-zeroes its heads each launch,
// so every graph replay starts clean. g_next needs no cleanup (fully
// rewritten by build_chains each launch before any read).
__device__ int g_head[NVOX];
__device__ int g_next[NPRIME_];

// ---------------------------------------------------------------------------
// Pass 1: build per-voxel linked lists of point indices. ~5 MB traffic.
// ---------------------------------------------------------------------------
__global__ __launch_bounds__(256) void build_chains(const int* __restrict__ geom)
{
    const int p = blockIdx.x * 256 + threadIdx.x;
    if (p >= NPRIME_) return;
    const int4 g = __ldg(reinterpret_cast<const int4*>(geom) + p);
    const int vox = (g.w * NX_ + g.x) * NY_ + g.y;   // gz==0 (NZ=1)
    const int old = atomicExch(&g_head[vox], p + 1);
    g_next[p] = old;
}

// ---------------------------------------------------------------------------
// Pass 2: gather + transpose. Block = 32 voxel rows x 256 channels.
// Each 64-thread group owns rows {4k + tid>>6}; for each row it walks the
// point chain (uniform within the group), accumulating float4 partial sums
// in registers (x row reads: 1KB coalesced LDG.128). Then the proven
// XOR-swizzled smem transpose writes each channel's 32 s-values as one
// complete 128B output line. Untouched rows emit zeros (head==0).
// Heads are re-zeroed for the next replay.
// ---------------------------------------------------------------------------
__global__ __launch_bounds__(256) void gather_transpose_kernel(
    const float* __restrict__ x,
    float* __restrict__ out)
{
    __shared__ float4 tile4[32][64];          // [s-row][swizzled channel-quad]
    __shared__ int heads[32];

    const int blk = blockIdx.x;               // 0 .. NVOX/32-1
    const int b   = blk / (S_ / 32);
    const int s0  = (blk % (S_ / 32)) * 32;
    const int tid = threadIdx.x;

    if (tid < 32) {
        const int v = b * S_ + s0 + tid;
        heads[tid] = g_head[v];
        g_head[v] = 0;                        // re-arm for next replay
    }
    __syncthreads();

    const int trow0 = tid >> 6;               // 0..3
    const int tcq   = tid & 63;               // channel quad 0..63

    float4 v[8];
    #pragma unroll
    for (int k = 0; k < 8; k++)
        v[k] = make_float4(0.f, 0.f, 0.f, 0.f);

    // Gather: walk each row's chain. h is uniform across the 64-thread group.
    #pragma unroll
    for (int k = 0; k < 8; k++) {
        const int row = 4 * k + trow0;
        int h = heads[row];
        while (h) {
            const float4 xv =
                __ldg(reinterpret_cast<const float4*>(x + (size_t)(h - 1) * C_) + tcq);
            v[k].x += xv.x;
            v[k].y += xv.y;
            v[k].z += xv.z;
            v[k].w += xv.w;
            h = __ldg(g_next + (h - 1));      // uniform broadcast load
        }
    }

    // Stage to smem, XOR-swizzled: tile4[row][tcq ^ (row>>2)].
    #pragma unroll
    for (int k = 0; k < 8; k++)
        tile4[4 * k + trow0][tcq ^ k] = v[k];

    __syncthreads();

    // Store phase: warp w, lane l; q = l&7 (s-quad), cu = l>>3.
    // Iteration i: channel c = 4*(w*8+i) + cu. Reads tile4[4q+r][cq ^ q]
    // component cu -> bank-conflict-free; each STG.128 warp-phase fills
    // 4 complete 128B output lines.
    const int w  = tid >> 5;
    const int l  = tid & 31;
    const int q  = l & 7;
    const int cu = l >> 3;

    float* dstb = out + (size_t)b * C_ * S_ + s0;

    #pragma unroll
    for (int i = 0; i < 8; i++) {
        const int cq = w * 8 + i;
        const int c  = 4 * cq + cu;
        float4 o;
        o.x = reinterpret_cast<const float*>(&tile4[4 * q + 0][cq ^ q])[cu];
        o.y = reinterpret_cast<const float*>(&tile4[4 * q + 1][cq ^ q])[cu];
        o.z = reinterpret_cast<const float*>(&tile4[4 * q + 2][cq ^ q])[cu];
        o.w = reinterpret_cast<const float*>(&tile4[4 * q + 3][cq ^ q])[cu];
        *reinterpret_cast<float4*>(dstb + (size_t)c * S_ + 4 * q) = o;
    }
}

extern "C" void kernel_launch(void* const* d_in, const int* in_sizes, int n_in,
                              void* d_out, int out_size)
{
    const float* x    = (const float*)d_in[0];   // [NPRIME, C] float32
    const int*   geom = (const int*)  d_in[1];   // [NPRIME, 4] int32
    float*       out  = (float*)d_out;           // [B, C, NX, NY] float32

    build_chains<<<(NPRIME_ + 255) / 256, 256>>>(geom);
    gather_transpose_kernel<<<NVOX / 32, 256>>>(x, out);
}

// round 9
// speedup vs baseline: 9.8379x; 1.1292x over previous
#include <cuda_runtime.h>
#include <cuda_bf16.h>
#include <cstdint>

// Problem constants (fixed shapes from reference)
#define B_     4
#define NX_    400
#define NY_    200
#define NZ_    1
#define C_     256
#define NPRIME_ 173184                            // B*6*41*8*22
#define S_      (NX_ * NY_)                       // 80000
#define NVOX    (B_ * S_)                         // 320000

// Per-voxel point chains. g_head: 0 = empty, else point_index+1.
// Zero at module load; the gather pass re-zeroes its heads each launch,
// so every graph replay starts clean. g_next is fully rewritten by
// build_chains each launch before any read.
__device__ int g_head[NVOX];
__device__ int g_next[NPRIME_];

// ---------------------------------------------------------------------------
// Pass 1: build per-voxel linked lists of point indices. ~5 MB traffic.
// ---------------------------------------------------------------------------
__global__ __launch_bounds__(256) void build_chains(const int* __restrict__ geom)
{
    const int p = blockIdx.x * 256 + threadIdx.x;
    if (p >= NPRIME_) return;
    const int4 g = __ldg(reinterpret_cast<const int4*>(geom) + p);
    const int vox = (g.w * NX_ + g.x) * NY_ + g.y;   // gz==0 (NZ=1)
    const int old = atomicExch(&g_head[vox], p + 1);
    g_next[p] = old;
}

// ---------------------------------------------------------------------------
// Pass 2: gather + transpose. Block = 32 voxel rows x 256 channels.
// Each 64-thread group owns 8 rows, processed as two 4-row half-batches:
// the FIRST chain step of all 4 rows is issued as one batch of independent
// loads (4x next + 4x float4 of x -> MLP~8, covers ~90% of points), then
// residual chain tails (rare; lambda=0.54) are walked sequentially.
// Store phase: XOR-swizzled smem transpose; each channel's 32 s-values
// form one complete 128B output line. Heads re-zeroed for next replay.
// ---------------------------------------------------------------------------
__global__ __launch_bounds__(256) void gather_transpose_kernel(
    const float* __restrict__ x,
    float* __restrict__ out)
{
    __shared__ float4 tile4[32][64];          // [s-row][swizzled channel-quad]
    __shared__ int heads[32];

    const int blk = blockIdx.x;               // 0 .. NVOX/32-1
    const int b   = blk / (S_ / 32);
    const int s0  = (blk % (S_ / 32)) * 32;
    const int tid = threadIdx.x;

    if (tid < 32) {
        const int v = b * S_ + s0 + tid;
        heads[tid] = g_head[v];
        g_head[v] = 0;                        // re-arm for next replay
    }
    __syncthreads();

    const int trow0 = tid >> 6;               // 0..3
    const int tcq   = tid & 63;               // channel quad 0..63
    const float4 zero4 = make_float4(0.f, 0.f, 0.f, 0.f);

    #pragma unroll
    for (int half = 0; half < 2; half++) {
        int    h[4];
        int    nx[4];
        float4 xv[4];

        #pragma unroll
        for (int k0 = 0; k0 < 4; k0++)
            h[k0] = heads[4 * (half * 4 + k0) + trow0];

        // Batched first step: all loads independent -> front-batched LDGs.
        #pragma unroll
        for (int k0 = 0; k0 < 4; k0++) {
            if (h[k0]) {
                nx[k0] = __ldg(g_next + (h[k0] - 1));
                xv[k0] = __ldg(reinterpret_cast<const float4*>(
                                   x + (size_t)(h[k0] - 1) * C_) + tcq);
            } else {
                nx[k0] = 0;
                xv[k0] = zero4;
            }
        }

        // Residual chain tails (rare): sequential walk, accumulate into xv.
        #pragma unroll
        for (int k0 = 0; k0 < 4; k0++) {
            int hh = nx[k0];
            while (hh) {
                const float4 t = __ldg(reinterpret_cast<const float4*>(
                                           x + (size_t)(hh - 1) * C_) + tcq);
                xv[k0].x += t.x;
                xv[k0].y += t.y;
                xv[k0].z += t.z;
                xv[k0].w += t.w;
                hh = __ldg(g_next + (hh - 1));
            }
        }

        // Stage to smem, XOR-swizzled: tile4[row][tcq ^ (row>>2)].
        #pragma unroll
        for (int k0 = 0; k0 < 4; k0++) {
            const int k = half * 4 + k0;
            tile4[4 * k + trow0][tcq ^ k] = xv[k0];
        }
    }

    __syncthreads();

    // Store phase: warp w, lane l; q = l&7 (s-quad), cu = l>>3.
    // Iteration i: channel c = 4*(w*8+i) + cu. Reads tile4[4q+r][cq ^ q]
    // component cu -> bank-conflict-free; each STG.128 warp-phase fills
    // 4 complete 128B output lines.
    const int w  = tid >> 5;
    const int l  = tid & 31;
    const int q  = l & 7;
    const int cu = l >> 3;

    float* dstb = out + (size_t)b * C_ * S_ + s0;

    #pragma unroll
    for (int i = 0; i < 8; i++) {
        const int cq = w * 8 + i;
        const int c  = 4 * cq + cu;
        float4 o;
        o.x = reinterpret_cast<const float*>(&tile4[4 * q + 0][cq ^ q])[cu];
        o.y = reinterpret_cast<const float*>(&tile4[4 * q + 1][cq ^ q])[cu];
        o.z = reinterpret_cast<const float*>(&tile4[4 * q + 2][cq ^ q])[cu];
        o.w = reinterpret_cast<const float*>(&tile4[4 * q + 3][cq ^ q])[cu];
        *reinterpret_cast<float4*>(dstb + (size_t)c * S_ + 4 * q) = o;
    }
}

extern "C" void kernel_launch(void* const* d_in, const int* in_sizes, int n_in,
                              void* d_out, int out_size)
{
    const float* x    = (const float*)d_in[0];   // [NPRIME, C] float32
    const int*   geom = (const int*)  d_in[1];   // [NPRIME, 4] int32
    float*       out  = (float*)d_out;           // [B, C, NX, NY] float32

    build_chains<<<(NPRIME_ + 255) / 256, 256>>>(geom);
    gather_transpose_kernel<<<NVOX / 32, 256>>>(x, out);
}

// round 10
// speedup vs baseline: 12.3550x; 1.2559x over previous
#include <cuda_runtime.h>
#include <cuda_bf16.h>
#include <cstdint>

// Problem constants (fixed shapes from reference)
#define B_     4
#define NX_    400
#define NY_    200
#define NZ_    1
#define C_     256
#define NPRIME_ 173184                            // B*6*41*8*22
#define S_      (NX_ * NY_)                       // 80000
#define NVOX    (B_ * S_)                         // 320000

// Per-voxel point chains. g_head: 0 = empty, else point_index+1.
// clear_heads zeroes g_head at the start of every launch, so no state is
// carried between graph replays. g_next is fully rewritten by build_chains.
__device__ int g_head[NVOX];
__device__ int g_next[NPRIME_];

// ---------------------------------------------------------------------------
// Pass 0: clear heads (1.3 MB, vectorized).
// ---------------------------------------------------------------------------
__global__ __launch_bounds__(256) void clear_heads()
{
    const int i = blockIdx.x * 256 + threadIdx.x;
    if (i < NVOX / 4)
        reinterpret_cast<int4*>(g_head)[i] = make_int4(0, 0, 0, 0);
}

// ---------------------------------------------------------------------------
// Pass 1: build per-voxel linked lists of point indices. ~5 MB traffic.
// ---------------------------------------------------------------------------
__global__ __launch_bounds__(256) void build_chains(const int* __restrict__ geom)
{
    const int p = blockIdx.x * 256 + threadIdx.x;
    if (p >= NPRIME_) return;
    const int4 g = __ldg(reinterpret_cast<const int4*>(geom) + p);
    const int vox = (g.w * NX_ + g.x) * NY_ + g.y;   // gz==0 (NZ=1)
    const int old = atomicExch(&g_head[vox], p + 1);
    g_next[p] = old;
}

// ---------------------------------------------------------------------------
// Pass 2: gather + transpose. Block = 32 voxel rows x 128 channels
// (blockIdx.y selects the channel half). Tile is 16 KB -> 8 blocks/SM
// (2048 threads, 100% occupancy target via __launch_bounds__(256,8)).
// Warp g owns rows {8k+g}; its 4 first chain steps are issued as ONE batch
// (4x LDG.128 + 4x LDG.32 in flight), covering ~90% of points; rare chain
// tails walked sequentially. XOR-swizzled smem transpose then emits each
// channel's 32 s-values as one complete 128B output line.
// ---------------------------------------------------------------------------
__global__ __launch_bounds__(256, 8) void gather_transpose_kernel(
    const float* __restrict__ x,
    float* __restrict__ out)
{
    __shared__ float4 tile4[32][32];          // [s-row][swizzled channel-quad]
    __shared__ int heads[32];

    const int blk  = blockIdx.x;              // 0 .. NVOX/32-1
    const int half = blockIdx.y;              // channel half: 0 or 1
    const int b    = blk / (S_ / 32);
    const int s0   = (blk % (S_ / 32)) * 32;
    const int tid  = threadIdx.x;

    if (tid < 32) heads[tid] = g_head[b * S_ + s0 + tid];
    __syncthreads();

    const int g    = tid >> 5;                // warp id 0..7 -> rows 8k+g
    const int cq0  = tid & 31;                // channel quad within half
    const int qidx = half * 32 + cq0;         // float4 index into point row
    const float4 zero4 = make_float4(0.f, 0.f, 0.f, 0.f);

    int    h[4];
    int    nx[4];
    float4 acc[4];

    #pragma unroll
    for (int k = 0; k < 4; k++)
        h[k] = heads[8 * k + g];

    // Single batched first step: 8 independent loads in flight.
    #pragma unroll
    for (int k = 0; k < 4; k++) {
        if (h[k]) {
            nx[k]  = __ldg(g_next + (h[k] - 1));
            acc[k] = __ldg(reinterpret_cast<const float4*>(
                               x + (size_t)(h[k] - 1) * C_) + qidx);
        } else {
            nx[k]  = 0;
            acc[k] = zero4;
        }
    }

    // Residual chain tails (rare; lambda = 0.54): sequential walk.
    #pragma unroll
    for (int k = 0; k < 4; k++) {
        int hh = nx[k];
        while (hh) {
            const float4 t = __ldg(reinterpret_cast<const float4*>(
                                       x + (size_t)(hh - 1) * C_) + qidx);
            acc[k].x += t.x;
            acc[k].y += t.y;
            acc[k].z += t.z;
            acc[k].w += t.w;
            hh = __ldg(g_next + (hh - 1));
        }
    }

    // Stage to smem, XOR-swizzled: tile4[row][cq0 ^ (row>>2)].
    #pragma unroll
    for (int k = 0; k < 4; k++) {
        const int row = 8 * k + g;
        tile4[row][cq0 ^ (row >> 2)] = acc[k];
    }

    __syncthreads();

    // Store phase: warp w, lane l; q = l&7 (s-quad), cu = l>>3.
    // Iteration i: cq = w*4+i, channel c = 4*cq+cu. Reads tile4[4q+r][cq^q]
    // component cu -> bank-bijective over 32 lanes (conflict-free); each
    // STG.128 warp-phase fills 4 complete 128B output lines.
    const int w  = tid >> 5;
    const int l  = tid & 31;
    const int q  = l & 7;
    const int cu = l >> 3;

    float* dstb = out + (size_t)b * C_ * S_ + (size_t)(half * 128) * S_ + s0;

    #pragma unroll
    for (int i = 0; i < 4; i++) {
        const int cq = w * 4 + i;
        const int c  = 4 * cq + cu;
        float4 o;
        o.x = reinterpret_cast<const float*>(&tile4[4 * q + 0][cq ^ q])[cu];
        o.y = reinterpret_cast<const float*>(&tile4[4 * q + 1][cq ^ q])[cu];
        o.z = reinterpret_cast<const float*>(&tile4[4 * q + 2][cq ^ q])[cu];
        o.w = reinterpret_cast<const float*>(&tile4[4 * q + 3][cq ^ q])[cu];
        *reinterpret_cast<float4*>(dstb + (size_t)c * S_ + 4 * q) = o;
    }
}

extern "C" void kernel_launch(void* const* d_in, const int* in_sizes, int n_in,
                              void* d_out, int out_size)
{
    const float* x    = (const float*)d_in[0];   // [NPRIME, C] float32
    const int*   geom = (const int*)  d_in[1];   // [NPRIME, 4] int32
    float*       out  = (float*)d_out;           // [B, C, NX, NY] float32

    clear_heads<<<(NVOX / 4 + 255) / 256, 256>>>();
    build_chains<<<(NPRIME_ + 255) / 256, 256>>>(geom);

    dim3 grid(NVOX / 32, 2);
    gather_transpose_kernel<<<grid, 256>>>(x, out);
}